// round 11
// baseline (speedup 1.0000x reference)
#include <cuda_runtime.h>
#include <math.h>
#include <stdint.h>

#define BATCH 4
#define SEQ   1024
#define DM    1024
#define NH    16
#define HD    64
#define BH    (BATCH*NH)

// Scratch (device globals: allocation-free per harness rules)
__device__ float g_rq [BATCH*SEQ*DM];           // tf32-rounded inputs
__device__ float g_rk [BATCH*SEQ*DM];
__device__ float g_rv [BATCH*SEQ*DM];
__device__ float g_rWq[DM*DM];
__device__ float g_rWk[DM*DM];
__device__ float g_rWv[DM*DM];
__device__ float g_rWo[DM*DM];
__device__ float g_Qh [BATCH*NH*SEQ*HD];        // [B,H,S,hd]  (tf32-rounded)
__device__ float g_Kh [BATCH*NH*SEQ*HD];        // [B,H,S,hd]  (tf32-rounded)
__device__ float g_VhT[BATCH*NH*HD*SEQ];        // [B,H,hd,S]  (tf32-rounded)
__device__ float g_AO [BATCH*SEQ*DM];           // [B,S,D] attn out (tf32-rounded)
__device__ float g_PE [SEQ*HD];                 // sinusoidal PE table

// ---------------------------------------------------------------------------
__device__ __forceinline__ uint32_t f2tf32(float x) {
    uint32_t r;
    asm("cvt.rna.tf32.f32 %0, %1;" : "=r"(r) : "f"(x));
    return r;
}
__device__ __forceinline__ float tfr(float x) { return __uint_as_float(f2tf32(x)); }

__device__ __forceinline__ void mma8(float* c, const uint32_t* a, const uint32_t* b) {
    asm volatile(
        "mma.sync.aligned.m16n8k8.row.col.f32.tf32.tf32.f32 "
        "{%0,%1,%2,%3},{%4,%5,%6,%7},{%8,%9},{%0,%1,%2,%3};"
        : "+f"(c[0]), "+f"(c[1]), "+f"(c[2]), "+f"(c[3])
        : "r"(a[0]), "r"(a[1]), "r"(a[2]), "r"(a[3]), "r"(b[0]), "r"(b[1]));
}

__device__ __forceinline__ void cpasync16(uint32_t dst, const void* src) {
    asm volatile("cp.async.cg.shared.global [%0], [%1], 16;" :: "r"(dst), "l"(src));
}
__device__ __forceinline__ void cp_commit() { asm volatile("cp.async.commit_group;"); }
template<int N>
__device__ __forceinline__ void cp_wait() {
    asm volatile("cp.async.wait_group %0;" :: "n"(N));
}

// ---------------------------------------------------------------------------
// PE table
// ---------------------------------------------------------------------------
__global__ void pe_init_kernel() {
    int idx = blockIdx.x * blockDim.x + threadIdx.x;
    if (idx >= SEQ * HD) return;
    int s = idx >> 6;
    int d = idx & 63;
    int de = d & ~1;
    float div = expf(-(float)de * 0.14391156831212787f);   // ln(10000)/64
    float ang = (float)s * div;
    g_PE[idx] = (d & 1) ? cosf(ang) : sinf(ang);
}

// ---------------------------------------------------------------------------
// Prep: round all GEMM operands to tf32-rna once. grid (4096, 7)
// ---------------------------------------------------------------------------
__global__ void prep_kernel(const float4* __restrict__ q, const float4* __restrict__ k,
                            const float4* __restrict__ v,
                            const float4* __restrict__ wq, const float4* __restrict__ wk,
                            const float4* __restrict__ wv, const float4* __restrict__ wo) {
    int i = blockIdx.x * blockDim.x + threadIdx.x;
    int z = blockIdx.y;
    const float4* src;
    float4* dst;
    int n4;
    switch (z) {
        case 0: src = q;  dst = (float4*)g_rq;  n4 = BATCH*SEQ*DM/4; break;
        case 1: src = k;  dst = (float4*)g_rk;  n4 = BATCH*SEQ*DM/4; break;
        case 2: src = v;  dst = (float4*)g_rv;  n4 = BATCH*SEQ*DM/4; break;
        case 3: src = wq; dst = (float4*)g_rWq; n4 = DM*DM/4; break;
        case 4: src = wk; dst = (float4*)g_rWk; n4 = DM*DM/4; break;
        case 5: src = wv; dst = (float4*)g_rWv; n4 = DM*DM/4; break;
        default:src = wo; dst = (float4*)g_rWo; n4 = DM*DM/4; break;
    }
    if (i >= n4) return;
    float4 a = src[i];
    dst[i] = make_float4(tfr(a.x), tfr(a.y), tfr(a.z), tfr(a.w));
}

// ---------------------------------------------------------------------------
// NT GEMM mainloop: acc = A[128,:] @ B[128,:]^T over K=1024.
// Inputs PRE-ROUNDED tf32 -> cp.async raw staging, 3-stage pipeline.
// CTA 128x128, KC=16, 256 thr, 8 warps 4(m)x2(n), warp tile 32x64.
// ---------------------------------------------------------------------------
__device__ __forceinline__ void gemm_mainloop(
    const float* __restrict__ A, const float* __restrict__ B,
    int cm, int cn, float (*As)[2048], float (*Bs)[2048], float acc[2][8][4])
{
    constexpr int K  = 1024;
    constexpr int KT = K / 16;

    const int tid  = threadIdx.x;
    const int arow = tid >> 2;          // 0..63
    const int ac4  = tid & 3;
    const uint32_t co = (uint32_t)((ac4 ^ ((arow >> 1) & 3)) << 4);  // byte ofs in row

    const float* pA0 = A + (size_t)(cm + arow)      * K + ac4 * 4;
    const float* pA1 = A + (size_t)(cm + arow + 64) * K + ac4 * 4;
    const float* pB0 = B + (size_t)(cn + arow)      * K + ac4 * 4;
    const float* pB1 = B + (size_t)(cn + arow + 64) * K + ac4 * 4;

    const uint32_t sA = (uint32_t)__cvta_generic_to_shared(As) + arow * 64 + co;
    const uint32_t sB = (uint32_t)__cvta_generic_to_shared(Bs) + arow * 64 + co;

    const int wid  = tid >> 5;
    const int lane = tid & 31;
    const int gid  = lane >> 2;
    const int tg   = lane & 3;
    const int wm = (wid & 3) * 32;
    const int wn = (wid >> 2) * 64;

    const int kx4 = ((gid >> 1) & 3) << 2;
    int xoff[4];
#pragma unroll
    for (int j = 0; j < 4; j++) xoff[j] = ((j << 2) ^ kx4) + tg;
    const int baseA = (wm + gid) * 16;
    const int baseB = (wn + gid) * 16;

#pragma unroll
    for (int i = 0; i < 2; i++)
#pragma unroll
        for (int j = 0; j < 8; j++)
#pragma unroll
            for (int l = 0; l < 4; l++) acc[i][j][l] = 0.f;

    // prologue: stages 0,1
#pragma unroll
    for (int s = 0; s < 2; s++) {
        const uint32_t so = (uint32_t)(s * 8192);
        cpasync16(sA + so,        pA0 + s * 16);
        cpasync16(sA + so + 4096, pA1 + s * 16);
        cpasync16(sB + so,        pB0 + s * 16);
        cpasync16(sB + so + 4096, pB1 + s * 16);
        cp_commit();
    }

    int stage = 0;
    for (int kt = 0; kt < KT; kt++) {
        if (kt + 2 < KT) cp_wait<1>(); else cp_wait<0>();
        __syncthreads();

        if (kt + 2 < KT) {
            int ns = stage + 2; if (ns >= 3) ns -= 3;
            const uint32_t so = (uint32_t)(ns * 8192);
            cpasync16(sA + so,        pA0 + (kt + 2) * 16);
            cpasync16(sA + so + 4096, pA1 + (kt + 2) * 16);
            cpasync16(sB + so,        pB0 + (kt + 2) * 16);
            cpasync16(sB + so + 4096, pB1 + (kt + 2) * 16);
            cp_commit();
        }

        const float* as_ = As[stage];
        const float* bs_ = Bs[stage];
#pragma unroll
        for (int kk = 0; kk < 2; kk++) {
            const int xa = xoff[2 * kk];
            const int xb = xoff[2 * kk + 1];
            uint32_t af[2][4], bf[8][2];
#pragma unroll
            for (int im = 0; im < 2; im++) {
                af[im][0] = __float_as_uint(as_[baseA + im * 256 +       xa]);
                af[im][1] = __float_as_uint(as_[baseA + im * 256 + 128 + xa]);
                af[im][2] = __float_as_uint(as_[baseA + im * 256 +       xb]);
                af[im][3] = __float_as_uint(as_[baseA + im * 256 + 128 + xb]);
            }
#pragma unroll
            for (int in_ = 0; in_ < 8; in_++) {
                bf[in_][0] = __float_as_uint(bs_[baseB + in_ * 128 + xa]);
                bf[in_][1] = __float_as_uint(bs_[baseB + in_ * 128 + xb]);
            }
#pragma unroll
            for (int im = 0; im < 2; im++)
#pragma unroll
                for (int in_ = 0; in_ < 8; in_++)
                    mma8(acc[im][in_], af[im], bf[in_]);
        }
        __syncthreads();
        if (++stage == 3) stage = 0;
    }
}

// ---------------------------------------------------------------------------
// Merged Q/K/V projection kernel: blockIdx.z selects the projection.
// ---------------------------------------------------------------------------
__global__ __launch_bounds__(256, 2)
void qkv_kernel2(const float* __restrict__ bq, const float* __restrict__ bk,
                 const float* __restrict__ bv) {
    __shared__ float As[3][2048];
    __shared__ float Bs[3][2048];

    const int z = blockIdx.z;
    const float* A    = (z == 0) ? g_rq  : (z == 1) ? g_rk  : g_rv;
    const float* B    = (z == 0) ? g_rWq : (z == 1) ? g_rWk : g_rWv;
    const float* bias = (z == 0) ? bq    : (z == 1) ? bk    : bv;

    const int cm = blockIdx.x * 128;
    const int cn = blockIdx.y * 128;

    float acc[2][8][4];
    gemm_mainloop(A, B, cm, cn, As, Bs, acc);

    const int tid = threadIdx.x;
    const int wid = tid >> 5, lane = tid & 31;
    const int gid = lane >> 2, tg = lane & 3;
    const int wm = (wid & 3) * 32, wn = (wid >> 2) * 64;

    float* dstQK = (z == 0) ? g_Qh : g_Kh;

#pragma unroll
    for (int im = 0; im < 2; im++) {
#pragma unroll
        for (int in_ = 0; in_ < 8; in_++) {
#pragma unroll
            for (int e = 0; e < 4; e++) {
                int m = cm + wm + im * 16 + gid + (e >> 1) * 8;
                int n = cn + wn + in_ * 8 + tg * 2 + (e & 1);
                float val = acc[im][in_][e];
                int b = m >> 10, s = m & 1023, h = n >> 6, d = n & 63;
                if (z == 2) {
                    val = tfr(val + bias[n]);
                    g_VhT[((size_t)((b * NH + h) * HD + d)) * SEQ + s] = val;
                } else {
                    val = tfr(val + bias[n] + g_PE[(s << 6) + d]);
                    dstQK[((size_t)((b * NH + h) * SEQ + s)) * HD + d] = val;
                }
            }
        }
    }
}

// ---------------------------------------------------------------------------
// Output projection: out = g_AO @ g_rWo^T + bo
// ---------------------------------------------------------------------------
__global__ __launch_bounds__(256, 2)
void oproj_kernel(const float* __restrict__ bo, float* __restrict__ out) {
    __shared__ float As[3][2048];
    __shared__ float Bs[3][2048];

    const int cm = blockIdx.x * 128;
    const int cn = blockIdx.y * 128;

    float acc[2][8][4];
    gemm_mainloop(g_AO, g_rWo, cm, cn, As, Bs, acc);

    const int tid = threadIdx.x;
    const int wid = tid >> 5, lane = tid & 31;
    const int gid = lane >> 2, tg = lane & 3;
    const int wm = (wid & 3) * 32, wn = (wid >> 2) * 64;

#pragma unroll
    for (int im = 0; im < 2; im++) {
#pragma unroll
        for (int in_ = 0; in_ < 8; in_++) {
            int r0 = cm + wm + im * 16 + gid;
            int c0 = cn + wn + in_ * 8 + tg * 2;
            out[(size_t)r0 * DM + c0]           = acc[im][in_][0] + bo[c0];
            out[(size_t)r0 * DM + c0 + 1]       = acc[im][in_][1] + bo[c0 + 1];
            out[(size_t)(r0 + 8) * DM + c0]     = acc[im][in_][2] + bo[c0];
            out[(size_t)(r0 + 8) * DM + c0 + 1] = acc[im][in_][3] + bo[c0 + 1];
        }
    }
}

// ---------------------------------------------------------------------------
// Flash attention. Block = 128 threads (4 warps), each warp owns 32 q-rows
// (two m16 tiles). B-fragments (K/V) loaded ONCE per kk and fed to two mmas
// -> half the LDS traffic per FLOP vs 16-row warps. P stays in registers.
// K/V staged by cp.async into swizzled stride-80 tiles, double-buffered.
// smem 80KB, ~222 regs -> 2 CTAs/SM.
// ---------------------------------------------------------------------------
#define KVS 80
#define FLASH_SMEM_BYTES (20480 * 4)

__global__ __launch_bounds__(128, 2)
void flash_kernel() {
    extern __shared__ float sm[];
    float* KsB = sm;                 // 2 x 5120
    float* VsB = sm + 10240;         // 2 x 5120

    const int tid  = threadIdx.x;
    const int lane = tid & 31;
    const int w    = tid >> 5;       // 0..3
    const int gid  = lane >> 2;
    const int tg   = lane & 3;
    const int qt   = blockIdx.x;
    const int bh   = blockIdx.y;

    const float* Qb = g_Qh  + (size_t)bh * (SEQ * HD);
    const float* Kb = g_Kh  + (size_t)bh * (SEQ * HD);
    const float* Vb = g_VhT + (size_t)bh * (HD * SEQ);

    // Q fragments, two m16 tiles, permuted k-cols (2tg, 2tg+1 per 8-group)
    uint32_t qf[2][8][4];
    {
        const float* q0 = Qb + (size_t)(qt * 128 + w * 32 + gid) * HD + 2 * tg;
#pragma unroll
        for (int im = 0; im < 2; im++) {
            const float* r0 = q0 + im * 16 * HD;
            const float* r1 = r0 + 8 * HD;
#pragma unroll
            for (int kk = 0; kk < 8; kk++) {
                float2 a = *(const float2*)(r0 + kk * 8);
                float2 b = *(const float2*)(r1 + kk * 8);
                qf[im][kk][0] = __float_as_uint(a.x);
                qf[im][kk][1] = __float_as_uint(b.x);
                qf[im][kk][2] = __float_as_uint(a.y);
                qf[im][kk][3] = __float_as_uint(b.y);
            }
        }
    }

    // cp.async staging: 128 thr -> 2 thr/row, 8 chunks of 16B each
    const int ln = tid >> 1;          // row 0..63
    const int hf = tid & 1;           // half of the 16-chunk row
    const int sw = ((ln >> 1) & 3) << 1;
    const uint32_t ksm = (uint32_t)__cvta_generic_to_shared(KsB) + ln * (KVS * 4);
    const uint32_t vsm = (uint32_t)__cvta_generic_to_shared(VsB) + ln * (KVS * 4);
    uint32_t co[8];
#pragma unroll
    for (int i = 0; i < 8; i++) co[i] = (uint32_t)(((hf * 8 + i) ^ sw) << 4);
    const float* kg = Kb + (size_t)ln * HD + hf * 32;
    const float* vg = Vb + (size_t)ln * SEQ + hf * 32;

    // prologue: stage tile 0 into buf 0
#pragma unroll
    for (int i = 0; i < 8; i++) {
        cpasync16(ksm + co[i], kg + i * 4);
        cpasync16(vsm + co[i], vg + i * 4);
    }
    cp_commit();
    cp_wait<0>();
    __syncthreads();

    float mx[4] = {-1e30f, -1e30f, -1e30f, -1e30f};
    float li[4] = {0.f, 0.f, 0.f, 0.f};
    float ao[2][8][4];
#pragma unroll
    for (int im = 0; im < 2; im++)
#pragma unroll
        for (int t = 0; t < 8; t++)
#pragma unroll
            for (int j = 0; j < 4; j++) ao[im][t][j] = 0.f;

    const int th  = tg >> 1;
    const int to  = 2 * (tg & 1);
    const int kxv = ((gid >> 1) & 3) << 1;
    const int rbase = gid * KVS;

    for (int kt = 0; kt < 16; kt++) {
        const int buf = kt & 1;
        if (kt < 15) {
            const float* kgn = kg + (size_t)(kt + 1) * 64 * HD;
            const float* vgn = vg + (kt + 1) * 64;
            const uint32_t kd = ksm + (uint32_t)((buf ^ 1) * 20480);
            const uint32_t vd = vsm + (uint32_t)((buf ^ 1) * 20480);
#pragma unroll
            for (int i = 0; i < 8; i++) {
                cpasync16(kd + co[i], kgn + i * 4);
                cpasync16(vd + co[i], vgn + i * 4);
            }
            cp_commit();
        }

        const float* ks = KsB + buf * 5120;
        const float* vs = VsB + buf * 5120;

        // S = Q @ K^T : both m16 tiles share each K fragment load
        float s[2][8][4];
#pragma unroll
        for (int im = 0; im < 2; im++)
#pragma unroll
            for (int t = 0; t < 8; t++)
#pragma unroll
                for (int j = 0; j < 4; j++) s[im][t][j] = 0.f;

#pragma unroll
        for (int kk = 0; kk < 8; kk++) {
            const int coff = ((((2 * kk + th) ^ kxv)) << 2) + to;
#pragma unroll
            for (int tn = 0; tn < 8; tn++) {
                float2 b = *(const float2*)(ks + tn * (8 * KVS) + rbase + coff);
                uint32_t bb[2] = { __float_as_uint(b.x), __float_as_uint(b.y) };
                mma8(s[0][tn], qf[0][kk], bb);
                mma8(s[1][tn], qf[1][kk], bb);
            }
        }

        // scale + row max (4 independent row-stat chains)
        float t0[4] = {-1e30f, -1e30f, -1e30f, -1e30f};
#pragma unroll
        for (int im = 0; im < 2; im++)
#pragma unroll
            for (int tn = 0; tn < 8; tn++) {
                s[im][tn][0] *= 0.125f; s[im][tn][1] *= 0.125f;
                s[im][tn][2] *= 0.125f; s[im][tn][3] *= 0.125f;
                t0[im*2]   = fmaxf(t0[im*2],   fmaxf(s[im][tn][0], s[im][tn][1]));
                t0[im*2+1] = fmaxf(t0[im*2+1], fmaxf(s[im][tn][2], s[im][tn][3]));
            }
#pragma unroll
        for (int r = 0; r < 4; r++) {
            t0[r] = fmaxf(t0[r], __shfl_xor_sync(0xffffffffu, t0[r], 1));
            t0[r] = fmaxf(t0[r], __shfl_xor_sync(0xffffffffu, t0[r], 2));
        }

        float mn[4], al[4], rs[4] = {0.f, 0.f, 0.f, 0.f};
#pragma unroll
        for (int r = 0; r < 4; r++) {
            mn[r] = fmaxf(mx[r], t0[r]);
            al[r] = __expf(mx[r] - mn[r]);
        }

#pragma unroll
        for (int im = 0; im < 2; im++)
#pragma unroll
            for (int tn = 0; tn < 8; tn++) {
                s[im][tn][0] = __expf(s[im][tn][0] - mn[im*2]);
                s[im][tn][1] = __expf(s[im][tn][1] - mn[im*2]);
                s[im][tn][2] = __expf(s[im][tn][2] - mn[im*2+1]);
                s[im][tn][3] = __expf(s[im][tn][3] - mn[im*2+1]);
                rs[im*2]   += s[im][tn][0] + s[im][tn][1];
                rs[im*2+1] += s[im][tn][2] + s[im][tn][3];
            }
#pragma unroll
        for (int r = 0; r < 4; r++) {
            rs[r] += __shfl_xor_sync(0xffffffffu, rs[r], 1);
            rs[r] += __shfl_xor_sync(0xffffffffu, rs[r], 2);
            li[r] = li[r] * al[r] + rs[r];
            mx[r] = mn[r];
        }
#pragma unroll
        for (int im = 0; im < 2; im++)
#pragma unroll
            for (int tn = 0; tn < 8; tn++) {
                ao[im][tn][0] *= al[im*2];   ao[im][tn][1] *= al[im*2];
                ao[im][tn][2] *= al[im*2+1]; ao[im][tn][3] *= al[im*2+1];
            }

        // O += P @ V : both tiles share each V fragment load
#pragma unroll
        for (int kc = 0; kc < 8; kc++) {
            uint32_t pa0[4] = { f2tf32(s[0][kc][0]), f2tf32(s[0][kc][2]),
                                f2tf32(s[0][kc][1]), f2tf32(s[0][kc][3]) };
            uint32_t pa1[4] = { f2tf32(s[1][kc][0]), f2tf32(s[1][kc][2]),
                                f2tf32(s[1][kc][1]), f2tf32(s[1][kc][3]) };
            const int coff = ((((2 * kc + th) ^ kxv)) << 2) + to;
#pragma unroll
            for (int tn = 0; tn < 8; tn++) {
                float2 b = *(const float2*)(vs + tn * (8 * KVS) + rbase + coff);
                uint32_t bb[2] = { __float_as_uint(b.x), __float_as_uint(b.y) };
                mma8(ao[0][tn], pa0, bb);
                mma8(ao[1][tn], pa1, bb);
            }
        }

        cp_wait<0>();
        __syncthreads();
    }

    // normalize + tf32-round + store to g_AO [B,S,D]
    int b = bh >> 4, h = bh & 15;
#pragma unroll
    for (int im = 0; im < 2; im++) {
        float i0 = 1.f / li[im*2], i1 = 1.f / li[im*2+1];
        size_t srow = (size_t)qt * 128 + w * 32 + im * 16 + gid;
        float* O0 = g_AO + ((size_t)b * SEQ + srow) * DM + h * HD + tg * 2;
        float* O1 = O0 + (size_t)8 * DM;
#pragma unroll
        for (int tn = 0; tn < 8; tn++) {
            *(float2*)(O0 + tn * 8) = make_float2(tfr(ao[im][tn][0] * i0), tfr(ao[im][tn][1] * i0));
            *(float2*)(O1 + tn * 8) = make_float2(tfr(ao[im][tn][2] * i1), tfr(ao[im][tn][3] * i1));
        }
    }
}

// ---------------------------------------------------------------------------
extern "C" void kernel_launch(void* const* d_in, const int* in_sizes, int n_in,
                              void* d_out, int out_size) {
    const float* q  = (const float*)d_in[0];
    const float* k  = (const float*)d_in[1];
    const float* v  = (const float*)d_in[2];
    const float* Wq = (const float*)d_in[3];
    const float* bq = (const float*)d_in[4];
    const float* Wk = (const float*)d_in[5];
    const float* bk = (const float*)d_in[6];
    const float* Wv = (const float*)d_in[7];
    const float* bv = (const float*)d_in[8];
    const float* Wo = (const float*)d_in[9];
    const float* bo = (const float*)d_in[10];
    float* out = (float*)d_out;

    cudaFuncSetAttribute(flash_kernel, cudaFuncAttributeMaxDynamicSharedMemorySize,
                         FLASH_SMEM_BYTES);

    pe_init_kernel<<<256, 256>>>();
    prep_kernel<<<dim3(4096, 7), 256>>>((const float4*)q, (const float4*)k,
                                        (const float4*)v, (const float4*)Wq,
                                        (const float4*)Wk, (const float4*)Wv,
                                        (const float4*)Wo);

    qkv_kernel2<<<dim3(32, 8, 3), 256>>>(bq, bk, bv);
    flash_kernel<<<dim3(8, 64), 128, FLASH_SMEM_BYTES>>>();
    oproj_kernel<<<dim3(32, 8), 256>>>(bo, out);
}

// round 13
// speedup vs baseline: 1.6475x; 1.6475x over previous
#include <cuda_runtime.h>
#include <cuda_fp16.h>
#include <math.h>
#include <stdint.h>

#define BATCH 4
#define SEQ   1024
#define DM    1024
#define NH    16
#define HD    64
#define BH    (BATCH*NH)

// Scratch (device globals: allocation-free per harness rules). All fp16.
__device__ __half g_rq [BATCH*SEQ*DM];
__device__ __half g_rk [BATCH*SEQ*DM];
__device__ __half g_rv [BATCH*SEQ*DM];
__device__ __half g_rWq[DM*DM];
__device__ __half g_rWk[DM*DM];
__device__ __half g_rWv[DM*DM];
__device__ __half g_rWo[DM*DM];
__device__ __half g_Qh [BATCH*NH*SEQ*HD];   // [B,H,S,hd]
__device__ __half g_Kh [BATCH*NH*SEQ*HD];   // [B,H,S,hd]
__device__ __half g_VhT[BATCH*NH*HD*SEQ];   // [B,H,hd,S]
__device__ __half g_AO [BATCH*SEQ*DM];      // [B,S,D]
__device__ float  g_PE [SEQ*HD];            // fp32 PE table

// ---------------------------------------------------------------------------
__device__ __forceinline__ uint32_t packh2(float a, float b) {
    __half2 h = __floats2half2_rn(a, b);
    return *reinterpret_cast<uint32_t*>(&h);
}

__device__ __forceinline__ void mma16(float* c, const uint32_t* a, const uint32_t* b) {
    asm volatile(
        "mma.sync.aligned.m16n8k16.row.col.f32.f16.f16.f32 "
        "{%0,%1,%2,%3},{%4,%5,%6,%7},{%8,%9},{%0,%1,%2,%3};"
        : "+f"(c[0]), "+f"(c[1]), "+f"(c[2]), "+f"(c[3])
        : "r"(a[0]), "r"(a[1]), "r"(a[2]), "r"(a[3]), "r"(b[0]), "r"(b[1]));
}

__device__ __forceinline__ void cpasync16(uint32_t dst, const void* src) {
    asm volatile("cp.async.cg.shared.global [%0], [%1], 16;" :: "r"(dst), "l"(src));
}
__device__ __forceinline__ void cp_commit() { asm volatile("cp.async.commit_group;"); }
template<int N>
__device__ __forceinline__ void cp_wait() {
    asm volatile("cp.async.wait_group %0;" :: "n"(N));
}

// ---------------------------------------------------------------------------
// PE table
// ---------------------------------------------------------------------------
__global__ void pe_init_kernel() {
    int idx = blockIdx.x * blockDim.x + threadIdx.x;
    if (idx >= SEQ * HD) return;
    int s = idx >> 6;
    int d = idx & 63;
    int de = d & ~1;
    float div = expf(-(float)de * 0.14391156831212787f);   // ln(10000)/64
    float ang = (float)s * div;
    g_PE[idx] = (d & 1) ? cosf(ang) : sinf(ang);
}

// ---------------------------------------------------------------------------
// Prep: round all GEMM operands to fp16 once. grid (4096, 7)
// ---------------------------------------------------------------------------
__global__ void prep_kernel(const float4* __restrict__ q, const float4* __restrict__ k,
                            const float4* __restrict__ v,
                            const float4* __restrict__ wq, const float4* __restrict__ wk,
                            const float4* __restrict__ wv, const float4* __restrict__ wo) {
    int i = blockIdx.x * blockDim.x + threadIdx.x;
    int z = blockIdx.y;
    const float4* src;
    __half* dst;
    int n4;
    switch (z) {
        case 0: src = q;  dst = g_rq;  n4 = BATCH*SEQ*DM/4; break;
        case 1: src = k;  dst = g_rk;  n4 = BATCH*SEQ*DM/4; break;
        case 2: src = v;  dst = g_rv;  n4 = BATCH*SEQ*DM/4; break;
        case 3: src = wq; dst = g_rWq; n4 = DM*DM/4; break;
        case 4: src = wk; dst = g_rWk; n4 = DM*DM/4; break;
        case 5: src = wv; dst = g_rWv; n4 = DM*DM/4; break;
        default:src = wo; dst = g_rWo; n4 = DM*DM/4; break;
    }
    if (i >= n4) return;
    float4 a = src[i];
    uint2 u;
    u.x = packh2(a.x, a.y);
    u.y = packh2(a.z, a.w);
    *reinterpret_cast<uint2*>(dst + 4 * i) = u;
}

// ---------------------------------------------------------------------------
// NT GEMM mainloop (fp16): acc = A[128,:] @ B[128,:]^T over K=1024.
// CTA 128x128, K-chunk 32 halfs (64B rows), 3-stage cp.async ring.
// 8 warps 4(m)x2(n), warp tile 32x64, mma m16n8k16.
// Smem rows of 32 halfs; 16B-chunk XOR swizzle key (r>>1)&3 ->
// fragment LDS.32 banks = 16(gid&1) + 4(chunk^key) + tg : conflict-free.
// ---------------------------------------------------------------------------
__device__ __forceinline__ void gemm_mainloop_h(
    const __half* __restrict__ A, const __half* __restrict__ B,
    int cm, int cn, __half (*As)[4096], __half (*Bs)[4096], float acc[2][8][4])
{
    constexpr int KT = 32;   // 1024 / 32

    const int tid = threadIdx.x;
    const int r   = tid >> 1;          // 0..127
    const int hh  = tid & 1;

    const __half* gA = A + (size_t)(cm + r) * 1024 + hh * 16;
    const __half* gB = B + (size_t)(cn + r) * 1024 + hh * 16;

    const uint32_t uA = (uint32_t)__cvta_generic_to_shared(As);
    const uint32_t uB = (uint32_t)__cvta_generic_to_shared(Bs);
    uint32_t so[2];
#pragma unroll
    for (int i = 0; i < 2; i++)
        so[i] = (uint32_t)(r * 64 + (((2 * hh + i) ^ ((r >> 1) & 3)) << 4));

    const int wid  = tid >> 5;
    const int lane = tid & 31;
    const int gid  = lane >> 2;
    const int tg   = lane & 3;
    const int wm = (wid & 3) * 32;
    const int wn = (wid >> 2) * 64;

    const int kx = (gid >> 1) & 3;
    int ck[4];
#pragma unroll
    for (int j = 0; j < 4; j++) ck[j] = ((j ^ kx) << 4);
    const int baseA = (wm + gid) * 64 + tg * 4;
    const int baseB = (wn + gid) * 64 + tg * 4;

#pragma unroll
    for (int i = 0; i < 2; i++)
#pragma unroll
        for (int j = 0; j < 8; j++)
#pragma unroll
            for (int l = 0; l < 4; l++) acc[i][j][l] = 0.f;

    // prologue: stages 0,1
#pragma unroll
    for (int s = 0; s < 2; s++) {
        const uint32_t sb = (uint32_t)(s * 8192);
#pragma unroll
        for (int i = 0; i < 2; i++) {
            cpasync16(uA + sb + so[i], gA + s * 32 + i * 8);
            cpasync16(uB + sb + so[i], gB + s * 32 + i * 8);
        }
        cp_commit();
    }

    int stage = 0;
    for (int c = 0; c < KT; c++) {
        if (c + 2 < KT) cp_wait<1>(); else cp_wait<0>();
        __syncthreads();

        if (c + 2 < KT) {
            int ns = stage + 2; if (ns >= 3) ns -= 3;
            const uint32_t sb = (uint32_t)(ns * 8192);
#pragma unroll
            for (int i = 0; i < 2; i++) {
                cpasync16(uA + sb + so[i], gA + (c + 2) * 32 + i * 8);
                cpasync16(uB + sb + so[i], gB + (c + 2) * 32 + i * 8);
            }
            cp_commit();
        }

        const char* as_ = (const char*)As[stage];
        const char* bs_ = (const char*)Bs[stage];
#pragma unroll
        for (int kk = 0; kk < 2; kk++) {
            const int c0o = ck[2 * kk];
            const int c1o = ck[2 * kk + 1];
            uint32_t af[2][4], bf[8][2];
#pragma unroll
            for (int im = 0; im < 2; im++) {
                const int ba = baseA + im * 1024;
                af[im][0] = *(const uint32_t*)(as_ + ba +       c0o);
                af[im][1] = *(const uint32_t*)(as_ + ba + 512 + c0o);
                af[im][2] = *(const uint32_t*)(as_ + ba +       c1o);
                af[im][3] = *(const uint32_t*)(as_ + ba + 512 + c1o);
            }
#pragma unroll
            for (int in_ = 0; in_ < 8; in_++) {
                bf[in_][0] = *(const uint32_t*)(bs_ + baseB + in_ * 512 + c0o);
                bf[in_][1] = *(const uint32_t*)(bs_ + baseB + in_ * 512 + c1o);
            }
#pragma unroll
            for (int im = 0; im < 2; im++)
#pragma unroll
                for (int in_ = 0; in_ < 8; in_++)
                    mma16(acc[im][in_], af[im], bf[in_]);
        }
        __syncthreads();
        if (++stage == 3) stage = 0;
    }
}

// ---------------------------------------------------------------------------
// Merged Q/K/V projection: blockIdx.z selects projection.
// ---------------------------------------------------------------------------
__global__ __launch_bounds__(256, 2)
void qkv_kernel(const float* __restrict__ bq, const float* __restrict__ bk,
                const float* __restrict__ bv) {
    __shared__ __half As[3][4096];
    __shared__ __half Bs[3][4096];

    const int z = blockIdx.z;
    const __half* A    = (z == 0) ? g_rq  : (z == 1) ? g_rk  : g_rv;
    const __half* B    = (z == 0) ? g_rWq : (z == 1) ? g_rWk : g_rWv;
    const float*  bias = (z == 0) ? bq    : (z == 1) ? bk    : bv;

    const int cm = blockIdx.x * 128;
    const int cn = blockIdx.y * 128;

    float acc[2][8][4];
    gemm_mainloop_h(A, B, cm, cn, As, Bs, acc);

    const int tid = threadIdx.x;
    const int wid = tid >> 5, lane = tid & 31;
    const int gid = lane >> 2, tg = lane & 3;
    const int wm = (wid & 3) * 32, wn = (wid >> 2) * 64;

    __half* dstQK = (z == 0) ? g_Qh : g_Kh;

#pragma unroll
    for (int im = 0; im < 2; im++) {
#pragma unroll
        for (int in_ = 0; in_ < 8; in_++) {
            const int c0 = cn + wn + in_ * 8 + tg * 2;
            const int h = c0 >> 6, d0 = c0 & 63;
            const float b0v = bias[c0], b1v = bias[c0 + 1];
#pragma unroll
            for (int rr = 0; rr < 2; rr++) {
                const int m = cm + wm + im * 16 + gid + rr * 8;
                const int b = m >> 10, s = m & 1023;
                float v0 = acc[im][in_][rr * 2];
                float v1 = acc[im][in_][rr * 2 + 1];
                if (z == 2) {
                    g_VhT[((size_t)(b * NH + h) * HD + d0)     * SEQ + s] = __float2half_rn(v0 + b0v);
                    g_VhT[((size_t)(b * NH + h) * HD + d0 + 1) * SEQ + s] = __float2half_rn(v1 + b1v);
                } else {
                    const float* pe = g_PE + s * 64 + d0;
                    uint32_t pk = packh2(v0 + b0v + pe[0], v1 + b1v + pe[1]);
                    *reinterpret_cast<uint32_t*>(
                        dstQK + ((size_t)(b * NH + h) * SEQ + s) * HD + d0) = pk;
                }
            }
        }
    }
}

// ---------------------------------------------------------------------------
// Output projection: out = g_AO @ g_rWo^T + bo (fp32 out)
// ---------------------------------------------------------------------------
__global__ __launch_bounds__(256, 2)
void oproj_kernel(const float* __restrict__ bo, float* __restrict__ out) {
    __shared__ __half As[3][4096];
    __shared__ __half Bs[3][4096];

    const int cm = blockIdx.x * 128;
    const int cn = blockIdx.y * 128;

    float acc[2][8][4];
    gemm_mainloop_h(g_AO, g_rWo, cm, cn, As, Bs, acc);

    const int tid = threadIdx.x;
    const int wid = tid >> 5, lane = tid & 31;
    const int gid = lane >> 2, tg = lane & 3;
    const int wm = (wid & 3) * 32, wn = (wid >> 2) * 64;

#pragma unroll
    for (int im = 0; im < 2; im++) {
#pragma unroll
        for (int in_ = 0; in_ < 8; in_++) {
            int r0 = cm + wm + im * 16 + gid;
            int c0 = cn + wn + in_ * 8 + tg * 2;
            out[(size_t)r0 * DM + c0]           = acc[im][in_][0] + bo[c0];
            out[(size_t)r0 * DM + c0 + 1]       = acc[im][in_][1] + bo[c0 + 1];
            out[(size_t)(r0 + 8) * DM + c0]     = acc[im][in_][2] + bo[c0];
            out[(size_t)(r0 + 8) * DM + c0 + 1] = acc[im][in_][3] + bo[c0 + 1];
        }
    }
}

// ---------------------------------------------------------------------------
// Flash attention (fp16). 128 thr, warp owns 32 q-rows (two m16 tiles).
// fp16 k16 fragments: QK C-frag maps NATIVELY to PV A-frag (no permutation).
// K/V tiles 64x64 halfs (128B rows, chunk XOR key r&7), double-buffered
// cp.async. Smem 32KB static -> 2 CTAs/SM.
// ---------------------------------------------------------------------------
__global__ __launch_bounds__(128, 2)
void flash_kernel() {
    __shared__ __half Ks[2][4096];
    __shared__ __half Vs[2][4096];

    const int tid  = threadIdx.x;
    const int lane = tid & 31;
    const int w    = tid >> 5;       // 0..3
    const int gid  = lane >> 2;
    const int tg   = lane & 3;
    const int qt   = blockIdx.x;
    const int bh   = blockIdx.y;

    const __half* Qb = g_Qh  + (size_t)bh * (SEQ * HD);
    const __half* Kb = g_Kh  + (size_t)bh * (SEQ * HD);
    const __half* Vb = g_VhT + (size_t)bh * (HD * SEQ);

    // Q fragments: qf[im][kk] = m16k16 A-frag (rows gid,gid+8; k pairs 2tg,2tg+8)
    uint32_t qf[2][4][4];
    {
#pragma unroll
        for (int im = 0; im < 2; im++) {
            const __half* r0 = Qb + (size_t)(qt * 128 + w * 32 + im * 16 + gid) * HD + 2 * tg;
            const __half* r1 = r0 + 8 * HD;
#pragma unroll
            for (int kk = 0; kk < 4; kk++) {
                qf[im][kk][0] = *(const uint32_t*)(r0 + kk * 16);
                qf[im][kk][1] = *(const uint32_t*)(r1 + kk * 16);
                qf[im][kk][2] = *(const uint32_t*)(r0 + kk * 16 + 8);
                qf[im][kk][3] = *(const uint32_t*)(r1 + kk * 16 + 8);
            }
        }
    }

    // cp.async staging: row r = tid>>1 (0..63), 4 chunks of 16B per thread
    const int r  = tid >> 1;
    const int hf = tid & 1;
    const uint32_t ksm = (uint32_t)__cvta_generic_to_shared(Ks) + r * 128;
    const uint32_t vsm = (uint32_t)__cvta_generic_to_shared(Vs) + r * 128;
    uint32_t co[4];
#pragma unroll
    for (int i = 0; i < 4; i++) co[i] = (uint32_t)((((4 * hf + i) ^ (r & 7)) << 4));
    const __half* kg = Kb + (size_t)r * HD + hf * 32;
    const __half* vg = Vb + (size_t)r * SEQ + hf * 32;

    // prologue: stage tile 0 into buf 0
#pragma unroll
    for (int i = 0; i < 4; i++) {
        cpasync16(ksm + co[i], kg + i * 8);
        cpasync16(vsm + co[i], vg + i * 8);
    }
    cp_commit();
    cp_wait<0>();
    __syncthreads();

    float mx[4] = {-1e30f, -1e30f, -1e30f, -1e30f};
    float li[4] = {0.f, 0.f, 0.f, 0.f};
    float ao[2][8][4];
#pragma unroll
    for (int im = 0; im < 2; im++)
#pragma unroll
        for (int t = 0; t < 8; t++)
#pragma unroll
            for (int j = 0; j < 4; j++) ao[im][t][j] = 0.f;

    const int rbase = gid * 128 + tg * 4;   // byte offset within tile row block
    int ckv[8];
#pragma unroll
    for (int j = 0; j < 8; j++) ckv[j] = ((j ^ gid) << 4);

    for (int kt = 0; kt < 16; kt++) {
        const int buf = kt & 1;
        if (kt < 15) {
            const __half* kgn = kg + (size_t)(kt + 1) * 64 * HD;
            const __half* vgn = vg + (kt + 1) * 64;
            const uint32_t kd = ksm + (uint32_t)((buf ^ 1) * 8192);
            const uint32_t vd = vsm + (uint32_t)((buf ^ 1) * 8192);
#pragma unroll
            for (int i = 0; i < 4; i++) {
                cpasync16(kd + co[i], kgn + i * 8);
                cpasync16(vd + co[i], vgn + i * 8);
            }
            cp_commit();
        }

        const char* ks = (const char*)Ks[buf];
        const char* vs = (const char*)Vs[buf];

        // S = Q @ K^T
        float s[2][8][4];
#pragma unroll
        for (int im = 0; im < 2; im++)
#pragma unroll
            for (int t = 0; t < 8; t++)
#pragma unroll
                for (int j = 0; j < 4; j++) s[im][t][j] = 0.f;

#pragma unroll
        for (int kk = 0; kk < 4; kk++) {
            const int c0o = ckv[2 * kk];
            const int c1o = ckv[2 * kk + 1];
#pragma unroll
            for (int tn = 0; tn < 8; tn++) {
                uint32_t bb[2];
                bb[0] = *(const uint32_t*)(ks + tn * 1024 + rbase + c0o);
                bb[1] = *(const uint32_t*)(ks + tn * 1024 + rbase + c1o);
                mma16(s[0][tn], qf[0][kk], bb);
                mma16(s[1][tn], qf[1][kk], bb);
            }
        }

        // scale + row max
        float t0[4] = {-1e30f, -1e30f, -1e30f, -1e30f};
#pragma unroll
        for (int im = 0; im < 2; im++)
#pragma unroll
            for (int tn = 0; tn < 8; tn++) {
                s[im][tn][0] *= 0.125f; s[im][tn][1] *= 0.125f;
                s[im][tn][2] *= 0.125f; s[im][tn][3] *= 0.125f;
                t0[im*2]   = fmaxf(t0[im*2],   fmaxf(s[im][tn][0], s[im][tn][1]));
                t0[im*2+1] = fmaxf(t0[im*2+1], fmaxf(s[im][tn][2], s[im][tn][3]));
            }
#pragma unroll
        for (int rr = 0; rr < 4; rr++) {
            t0[rr] = fmaxf(t0[rr], __shfl_xor_sync(0xffffffffu, t0[rr], 1));
            t0[rr] = fmaxf(t0[rr], __shfl_xor_sync(0xffffffffu, t0[rr], 2));
        }

        float mn[4], al[4], rs[4] = {0.f, 0.f, 0.f, 0.f};
#pragma unroll
        for (int rr = 0; rr < 4; rr++) {
            mn[rr] = fmaxf(mx[rr], t0[rr]);
            al[rr] = __expf(mx[rr] - mn[rr]);
        }

#pragma unroll
        for (int im = 0; im < 2; im++)
#pragma unroll
            for (int tn = 0; tn < 8; tn++) {
                s[im][tn][0] = __expf(s[im][tn][0] - mn[im*2]);
                s[im][tn][1] = __expf(s[im][tn][1] - mn[im*2]);
                s[im][tn][2] = __expf(s[im][tn][2] - mn[im*2+1]);
                s[im][tn][3] = __expf(s[im][tn][3] - mn[im*2+1]);
                rs[im*2]   += s[im][tn][0] + s[im][tn][1];
                rs[im*2+1] += s[im][tn][2] + s[im][tn][3];
            }
#pragma unroll
        for (int rr = 0; rr < 4; rr++) {
            rs[rr] += __shfl_xor_sync(0xffffffffu, rs[rr], 1);
            rs[rr] += __shfl_xor_sync(0xffffffffu, rs[rr], 2);
            li[rr] = li[rr] * al[rr] + rs[rr];
            mx[rr] = mn[rr];
        }
#pragma unroll
        for (int im = 0; im < 2; im++)
#pragma unroll
            for (int tn = 0; tn < 8; tn++) {
                ao[im][tn][0] *= al[im*2];   ao[im][tn][1] *= al[im*2];
                ao[im][tn][2] *= al[im*2+1]; ao[im][tn][3] *= al[im*2+1];
            }

        // O += P @ V  (C-frag -> fp16 A-frag natively: pa = {s[2kc]01, s[2kc]23, s[2kc+1]01, s[2kc+1]23})
#pragma unroll
        for (int kc = 0; kc < 4; kc++) {
            uint32_t pa0[4] = { packh2(s[0][2*kc][0],   s[0][2*kc][1]),
                                packh2(s[0][2*kc][2],   s[0][2*kc][3]),
                                packh2(s[0][2*kc+1][0], s[0][2*kc+1][1]),
                                packh2(s[0][2*kc+1][2], s[0][2*kc+1][3]) };
            uint32_t pa1[4] = { packh2(s[1][2*kc][0],   s[1][2*kc][1]),
                                packh2(s[1][2*kc][2],   s[1][2*kc][3]),
                                packh2(s[1][2*kc+1][0], s[1][2*kc+1][1]),
                                packh2(s[1][2*kc+1][2], s[1][2*kc+1][3]) };
            const int c0o = ckv[2 * kc];
            const int c1o = ckv[2 * kc + 1];
#pragma unroll
            for (int tn = 0; tn < 8; tn++) {
                uint32_t bb[2];
                bb[0] = *(const uint32_t*)(vs + tn * 1024 + rbase + c0o);
                bb[1] = *(const uint32_t*)(vs + tn * 1024 + rbase + c1o);
                mma16(ao[0][tn], pa0, bb);
                mma16(ao[1][tn], pa1, bb);
            }
        }

        cp_wait<0>();
        __syncthreads();
    }

    // normalize + fp16 store to g_AO [B,S,D]
    int b = bh >> 4, h = bh & 15;
#pragma unroll
    for (int im = 0; im < 2; im++) {
        float i0 = 1.f / li[im*2], i1 = 1.f / li[im*2+1];
        size_t srow = (size_t)qt * 128 + w * 32 + im * 16 + gid;
        __half* O0 = g_AO + ((size_t)b * SEQ + srow) * DM + h * HD + tg * 2;
        __half* O1 = O0 + (size_t)8 * DM;
#pragma unroll
        for (int tn = 0; tn < 8; tn++) {
            *reinterpret_cast<uint32_t*>(O0 + tn * 8) =
                packh2(ao[im][tn][0] * i0, ao[im][tn][1] * i0);
            *reinterpret_cast<uint32_t*>(O1 + tn * 8) =
                packh2(ao[im][tn][2] * i1, ao[im][tn][3] * i1);
        }
    }
}

// ---------------------------------------------------------------------------
extern "C" void kernel_launch(void* const* d_in, const int* in_sizes, int n_in,
                              void* d_out, int out_size) {
    const float* q  = (const float*)d_in[0];
    const float* k  = (const float*)d_in[1];
    const float* v  = (const float*)d_in[2];
    const float* Wq = (const float*)d_in[3];
    const float* bq = (const float*)d_in[4];
    const float* Wk = (const float*)d_in[5];
    const float* bk = (const float*)d_in[6];
    const float* Wv = (const float*)d_in[7];
    const float* bv = (const float*)d_in[8];
    const float* Wo = (const float*)d_in[9];
    const float* bo = (const float*)d_in[10];
    float* out = (float*)d_out;

    pe_init_kernel<<<256, 256>>>();
    prep_kernel<<<dim3(4096, 7), 256>>>((const float4*)q, (const float4*)k,
                                        (const float4*)v, (const float4*)Wq,
                                        (const float4*)Wk, (const float4*)Wv,
                                        (const float4*)Wo);

    qkv_kernel<<<dim3(32, 8, 3), 256>>>(bq, bk, bv);
    flash_kernel<<<dim3(8, 64), 128>>>();
    oproj_kernel<<<dim3(32, 8), 256>>>(bo, out);
}

// round 14
// speedup vs baseline: 1.7006x; 1.0322x over previous
#include <cuda_runtime.h>
#include <cuda_fp16.h>
#include <math.h>
#include <stdint.h>

#define BATCH 4
#define SEQ   1024
#define DM    1024
#define NH    16
#define HD    64
#define BH    (BATCH*NH)

// Scratch (device globals: allocation-free per harness rules). All fp16.
__device__ __half g_rq [BATCH*SEQ*DM];
__device__ __half g_rk [BATCH*SEQ*DM];
__device__ __half g_rv [BATCH*SEQ*DM];
__device__ __half g_rWq[DM*DM];
__device__ __half g_rWk[DM*DM];
__device__ __half g_rWv[DM*DM];
__device__ __half g_rWo[DM*DM];
__device__ __half g_Qh [BATCH*NH*SEQ*HD];   // [B,H,S,hd]
__device__ __half g_Kh [BATCH*NH*SEQ*HD];   // [B,H,S,hd]
__device__ __half g_VhT[BATCH*NH*HD*SEQ];   // [B,H,hd,S]
__device__ __half g_AO [BATCH*SEQ*DM];      // [B,S,D]
__device__ float  g_PE [SEQ*HD];            // fp32 PE table

// ---------------------------------------------------------------------------
__device__ __forceinline__ uint32_t packh2(float a, float b) {
    __half2 h = __floats2half2_rn(a, b);
    return *reinterpret_cast<uint32_t*>(&h);
}

__device__ __forceinline__ float ex2(float x) {
    float r;
    asm("ex2.approx.f32 %0, %1;" : "=f"(r) : "f"(x));
    return r;
}

__device__ __forceinline__ void mma16(float* c, const uint32_t* a, const uint32_t* b) {
    asm volatile(
        "mma.sync.aligned.m16n8k16.row.col.f32.f16.f16.f32 "
        "{%0,%1,%2,%3},{%4,%5,%6,%7},{%8,%9},{%0,%1,%2,%3};"
        : "+f"(c[0]), "+f"(c[1]), "+f"(c[2]), "+f"(c[3])
        : "r"(a[0]), "r"(a[1]), "r"(a[2]), "r"(a[3]), "r"(b[0]), "r"(b[1]));
}

__device__ __forceinline__ void cpasync16(uint32_t dst, const void* src) {
    asm volatile("cp.async.cg.shared.global [%0], [%1], 16;" :: "r"(dst), "l"(src));
}
__device__ __forceinline__ void cp_commit() { asm volatile("cp.async.commit_group;"); }
template<int N>
__device__ __forceinline__ void cp_wait() {
    asm volatile("cp.async.wait_group %0;" :: "n"(N));
}

// ---------------------------------------------------------------------------
// Prep: round all GEMM operands to fp16 + build PE table. grid (4096, 8)
// ---------------------------------------------------------------------------
__global__ void prep_kernel(const float4* __restrict__ q, const float4* __restrict__ k,
                            const float4* __restrict__ v,
                            const float4* __restrict__ wq, const float4* __restrict__ wk,
                            const float4* __restrict__ wv, const float4* __restrict__ wo) {
    int i = blockIdx.x * blockDim.x + threadIdx.x;
    int z = blockIdx.y;
    if (z == 7) {
        // PE: 4 consecutive elements per thread
        int idx = i * 4;
        if (idx >= SEQ * HD) return;
        int s = idx >> 6;
        float4 r;
        float* rp = &r.x;
#pragma unroll
        for (int j = 0; j < 4; j++) {
            int d = (idx + j) & 63;
            int de = d & ~1;
            float div = expf(-(float)de * 0.14391156831212787f);   // ln(10000)/64
            float ang = (float)s * div;
            rp[j] = (d & 1) ? cosf(ang) : sinf(ang);
        }
        *(float4*)(g_PE + idx) = r;
        return;
    }
    const float4* src;
    __half* dst;
    int n4;
    switch (z) {
        case 0: src = q;  dst = g_rq;  n4 = BATCH*SEQ*DM/4; break;
        case 1: src = k;  dst = g_rk;  n4 = BATCH*SEQ*DM/4; break;
        case 2: src = v;  dst = g_rv;  n4 = BATCH*SEQ*DM/4; break;
        case 3: src = wq; dst = g_rWq; n4 = DM*DM/4; break;
        case 4: src = wk; dst = g_rWk; n4 = DM*DM/4; break;
        case 5: src = wv; dst = g_rWv; n4 = DM*DM/4; break;
        default:src = wo; dst = g_rWo; n4 = DM*DM/4; break;
    }
    if (i >= n4) return;
    float4 a = src[i];
    uint2 u;
    u.x = packh2(a.x, a.y);
    u.y = packh2(a.z, a.w);
    *reinterpret_cast<uint2*>(dst + 4 * i) = u;
}

// ---------------------------------------------------------------------------
// NT GEMM mainloop (fp16): acc = A[128,:] @ B[128,:]^T over K=1024.
// CTA 128x128, K-chunk 64 halfs (128B rows), 3-stage cp.async ring (16 iters).
// 8 warps 4(m)x2(n), warp tile 32x64, mma m16n8k16.
// 128B rows, 16B-chunk XOR key row&7 -> fragment LDS.32 conflict-free.
// Dynamic smem: A 3x16KB | B 3x16KB = 96KB.
// ---------------------------------------------------------------------------
#define GEMM_SMEM_BYTES 98304

__device__ __forceinline__ void gemm_mainloop_h(
    const __half* __restrict__ A, const __half* __restrict__ B,
    int cm, int cn, float acc[2][8][4])
{
    extern __shared__ __half dsm[];
    __half* As = dsm;               // 3 x 8192 halfs
    __half* Bs = dsm + 3 * 8192;

    constexpr int KT = 16;   // 1024 / 64

    const int tid = threadIdx.x;
    const int r   = tid >> 1;          // 0..127
    const int hh  = tid & 1;           // half of 128B row

    const __half* gA = A + (size_t)(cm + r) * 1024 + hh * 32;
    const __half* gB = B + (size_t)(cn + r) * 1024 + hh * 32;

    const uint32_t uA = (uint32_t)__cvta_generic_to_shared(As);
    const uint32_t uB = (uint32_t)__cvta_generic_to_shared(Bs);
    uint32_t so[4];
#pragma unroll
    for (int i = 0; i < 4; i++)
        so[i] = (uint32_t)(r * 128 + (((4 * hh + i) ^ (r & 7)) << 4));

    const int wid  = tid >> 5;
    const int lane = tid & 31;
    const int gid  = lane >> 2;
    const int tg   = lane & 3;
    const int wm = (wid & 3) * 32;
    const int wn = (wid >> 2) * 64;

    int ck[8];
#pragma unroll
    for (int j = 0; j < 8; j++) ck[j] = ((j ^ gid) << 4);
    const int baseA0 = (wm + gid) * 128 + tg * 4;
    const int baseB0 = (wn + gid) * 128 + tg * 4;

#pragma unroll
    for (int i = 0; i < 2; i++)
#pragma unroll
        for (int j = 0; j < 8; j++)
#pragma unroll
            for (int l = 0; l < 4; l++) acc[i][j][l] = 0.f;

    // prologue: stages 0,1
#pragma unroll
    for (int s = 0; s < 2; s++) {
        const uint32_t sb = (uint32_t)(s * 16384);
#pragma unroll
        for (int i = 0; i < 4; i++) {
            cpasync16(uA + sb + so[i], gA + s * 64 + i * 8);
            cpasync16(uB + sb + so[i], gB + s * 64 + i * 8);
        }
        cp_commit();
    }

    int stage = 0;
    for (int c = 0; c < KT; c++) {
        if (c + 2 < KT) cp_wait<1>(); else cp_wait<0>();
        __syncthreads();

        if (c + 2 < KT) {
            int ns = stage + 2; if (ns >= 3) ns -= 3;
            const uint32_t sb = (uint32_t)(ns * 16384);
#pragma unroll
            for (int i = 0; i < 4; i++) {
                cpasync16(uA + sb + so[i], gA + (c + 2) * 64 + i * 8);
                cpasync16(uB + sb + so[i], gB + (c + 2) * 64 + i * 8);
            }
            cp_commit();
        }

        const char* as_ = (const char*)(As + stage * 8192);
        const char* bs_ = (const char*)(Bs + stage * 8192);
#pragma unroll
        for (int kk = 0; kk < 4; kk++) {
            const int c0o = ck[2 * kk];
            const int c1o = ck[2 * kk + 1];
            uint32_t af[2][4], bf[8][2];
#pragma unroll
            for (int im = 0; im < 2; im++) {
                const int ba = baseA0 + im * 2048;
                af[im][0] = *(const uint32_t*)(as_ + ba +        c0o);
                af[im][1] = *(const uint32_t*)(as_ + ba + 1024 + c0o);
                af[im][2] = *(const uint32_t*)(as_ + ba +        c1o);
                af[im][3] = *(const uint32_t*)(as_ + ba + 1024 + c1o);
            }
#pragma unroll
            for (int in_ = 0; in_ < 8; in_++) {
                bf[in_][0] = *(const uint32_t*)(bs_ + baseB0 + in_ * 1024 + c0o);
                bf[in_][1] = *(const uint32_t*)(bs_ + baseB0 + in_ * 1024 + c1o);
            }
#pragma unroll
            for (int im = 0; im < 2; im++)
#pragma unroll
                for (int in_ = 0; in_ < 8; in_++)
                    mma16(acc[im][in_], af[im], bf[in_]);
        }
        __syncthreads();
        if (++stage == 3) stage = 0;
    }
}

// ---------------------------------------------------------------------------
// Merged Q/K/V projection: blockIdx.z selects projection.
// ---------------------------------------------------------------------------
__global__ __launch_bounds__(256, 2)
void qkv_kernel(const float* __restrict__ bq, const float* __restrict__ bk,
                const float* __restrict__ bv) {
    const int z = blockIdx.z;
    const __half* A    = (z == 0) ? g_rq  : (z == 1) ? g_rk  : g_rv;
    const __half* B    = (z == 0) ? g_rWq : (z == 1) ? g_rWk : g_rWv;
    const float*  bias = (z == 0) ? bq    : (z == 1) ? bk    : bv;

    const int cm = blockIdx.x * 128;
    const int cn = blockIdx.y * 128;

    float acc[2][8][4];
    gemm_mainloop_h(A, B, cm, cn, acc);

    const int tid = threadIdx.x;
    const int wid = tid >> 5, lane = tid & 31;
    const int gid = lane >> 2, tg = lane & 3;
    const int wm = (wid & 3) * 32, wn = (wid >> 2) * 64;

    __half* dstQK = (z == 0) ? g_Qh : g_Kh;

#pragma unroll
    for (int im = 0; im < 2; im++) {
#pragma unroll
        for (int in_ = 0; in_ < 8; in_++) {
            const int c0 = cn + wn + in_ * 8 + tg * 2;
            const int h = c0 >> 6, d0 = c0 & 63;
            const float b0v = bias[c0], b1v = bias[c0 + 1];
#pragma unroll
            for (int rr = 0; rr < 2; rr++) {
                const int m = cm + wm + im * 16 + gid + rr * 8;
                const int b = m >> 10, s = m & 1023;
                float v0 = acc[im][in_][rr * 2];
                float v1 = acc[im][in_][rr * 2 + 1];
                if (z == 2) {
                    g_VhT[((size_t)(b * NH + h) * HD + d0)     * SEQ + s] = __float2half_rn(v0 + b0v);
                    g_VhT[((size_t)(b * NH + h) * HD + d0 + 1) * SEQ + s] = __float2half_rn(v1 + b1v);
                } else {
                    const float* pe = g_PE + s * 64 + d0;
                    uint32_t pk = packh2(v0 + b0v + pe[0], v1 + b1v + pe[1]);
                    *reinterpret_cast<uint32_t*>(
                        dstQK + ((size_t)(b * NH + h) * SEQ + s) * HD + d0) = pk;
                }
            }
        }
    }
}

// ---------------------------------------------------------------------------
// Output projection: out = g_AO @ g_rWo^T + bo (fp32 out)
// ---------------------------------------------------------------------------
__global__ __launch_bounds__(256, 2)
void oproj_kernel(const float* __restrict__ bo, float* __restrict__ out) {
    const int cm = blockIdx.x * 128;
    const int cn = blockIdx.y * 128;

    float acc[2][8][4];
    gemm_mainloop_h(g_AO, g_rWo, cm, cn, acc);

    const int tid = threadIdx.x;
    const int wid = tid >> 5, lane = tid & 31;
    const int gid = lane >> 2, tg = lane & 3;
    const int wm = (wid & 3) * 32, wn = (wid >> 2) * 64;

#pragma unroll
    for (int im = 0; im < 2; im++) {
#pragma unroll
        for (int in_ = 0; in_ < 8; in_++) {
            int r0 = cm + wm + im * 16 + gid;
            int c0 = cn + wn + in_ * 8 + tg * 2;
            out[(size_t)r0 * DM + c0]           = acc[im][in_][0] + bo[c0];
            out[(size_t)r0 * DM + c0 + 1]       = acc[im][in_][1] + bo[c0 + 1];
            out[(size_t)(r0 + 8) * DM + c0]     = acc[im][in_][2] + bo[c0];
            out[(size_t)(r0 + 8) * DM + c0 + 1] = acc[im][in_][3] + bo[c0 + 1];
        }
    }
}

// ---------------------------------------------------------------------------
// Flash attention (fp16). 128 thr, warp owns 32 q-rows (two m16 tiles).
// QK C-frag maps natively to PV A-frag. Softmax via folded ex2
// (C = 0.125*log2e) on RAW scores. K/V double-buffered cp.async.
// ---------------------------------------------------------------------------
#define SM_C 0.18033688011112042f   // 0.125 * log2(e)

__global__ __launch_bounds__(128, 2)
void flash_kernel() {
    __shared__ __half Ks[2][4096];
    __shared__ __half Vs[2][4096];

    const int tid  = threadIdx.x;
    const int lane = tid & 31;
    const int w    = tid >> 5;       // 0..3
    const int gid  = lane >> 2;
    const int tg   = lane & 3;
    const int qt   = blockIdx.x;
    const int bh   = blockIdx.y;

    const __half* Qb = g_Qh  + (size_t)bh * (SEQ * HD);
    const __half* Kb = g_Kh  + (size_t)bh * (SEQ * HD);
    const __half* Vb = g_VhT + (size_t)bh * (HD * SEQ);

    uint32_t qf[2][4][4];
    {
#pragma unroll
        for (int im = 0; im < 2; im++) {
            const __half* r0 = Qb + (size_t)(qt * 128 + w * 32 + im * 16 + gid) * HD + 2 * tg;
            const __half* r1 = r0 + 8 * HD;
#pragma unroll
            for (int kk = 0; kk < 4; kk++) {
                qf[im][kk][0] = *(const uint32_t*)(r0 + kk * 16);
                qf[im][kk][1] = *(const uint32_t*)(r1 + kk * 16);
                qf[im][kk][2] = *(const uint32_t*)(r0 + kk * 16 + 8);
                qf[im][kk][3] = *(const uint32_t*)(r1 + kk * 16 + 8);
            }
        }
    }

    const int r  = tid >> 1;
    const int hf = tid & 1;
    const uint32_t ksm = (uint32_t)__cvta_generic_to_shared(Ks) + r * 128;
    const uint32_t vsm = (uint32_t)__cvta_generic_to_shared(Vs) + r * 128;
    uint32_t co[4];
#pragma unroll
    for (int i = 0; i < 4; i++) co[i] = (uint32_t)((((4 * hf + i) ^ (r & 7)) << 4));
    const __half* kg = Kb + (size_t)r * HD + hf * 32;
    const __half* vg = Vb + (size_t)r * SEQ + hf * 32;

#pragma unroll
    for (int i = 0; i < 4; i++) {
        cpasync16(ksm + co[i], kg + i * 8);
        cpasync16(vsm + co[i], vg + i * 8);
    }
    cp_commit();
    cp_wait<0>();
    __syncthreads();

    float mx[4] = {-1e30f, -1e30f, -1e30f, -1e30f};
    float li[4] = {0.f, 0.f, 0.f, 0.f};
    float ao[2][8][4];
#pragma unroll
    for (int im = 0; im < 2; im++)
#pragma unroll
        for (int t = 0; t < 8; t++)
#pragma unroll
            for (int j = 0; j < 4; j++) ao[im][t][j] = 0.f;

    const int rbase = gid * 128 + tg * 4;
    int ckv[8];
#pragma unroll
    for (int j = 0; j < 8; j++) ckv[j] = ((j ^ gid) << 4);

    for (int kt = 0; kt < 16; kt++) {
        const int buf = kt & 1;
        if (kt < 15) {
            const __half* kgn = kg + (size_t)(kt + 1) * 64 * HD;
            const __half* vgn = vg + (kt + 1) * 64;
            const uint32_t kd = ksm + (uint32_t)((buf ^ 1) * 8192);
            const uint32_t vd = vsm + (uint32_t)((buf ^ 1) * 8192);
#pragma unroll
            for (int i = 0; i < 4; i++) {
                cpasync16(kd + co[i], kgn + i * 8);
                cpasync16(vd + co[i], vgn + i * 8);
            }
            cp_commit();
        }

        const char* ks = (const char*)Ks[buf];
        const char* vs = (const char*)Vs[buf];

        // S = Q @ K^T (raw scores)
        float s[2][8][4];
#pragma unroll
        for (int im = 0; im < 2; im++)
#pragma unroll
            for (int t = 0; t < 8; t++)
#pragma unroll
                for (int j = 0; j < 4; j++) s[im][t][j] = 0.f;

#pragma unroll
        for (int kk = 0; kk < 4; kk++) {
            const int c0o = ckv[2 * kk];
            const int c1o = ckv[2 * kk + 1];
#pragma unroll
            for (int tn = 0; tn < 8; tn++) {
                uint32_t bb[2];
                bb[0] = *(const uint32_t*)(ks + tn * 1024 + rbase + c0o);
                bb[1] = *(const uint32_t*)(ks + tn * 1024 + rbase + c1o);
                mma16(s[0][tn], qf[0][kk], bb);
                mma16(s[1][tn], qf[1][kk], bb);
            }
        }

        // row max over raw scores
        float t0[4] = {-1e30f, -1e30f, -1e30f, -1e30f};
#pragma unroll
        for (int im = 0; im < 2; im++)
#pragma unroll
            for (int tn = 0; tn < 8; tn++) {
                t0[im*2]   = fmaxf(t0[im*2],   fmaxf(s[im][tn][0], s[im][tn][1]));
                t0[im*2+1] = fmaxf(t0[im*2+1], fmaxf(s[im][tn][2], s[im][tn][3]));
            }
#pragma unroll
        for (int rr = 0; rr < 4; rr++) {
            t0[rr] = fmaxf(t0[rr], __shfl_xor_sync(0xffffffffu, t0[rr], 1));
            t0[rr] = fmaxf(t0[rr], __shfl_xor_sync(0xffffffffu, t0[rr], 2));
        }

        float mn[4], al[4], nmc[4], rs[4] = {0.f, 0.f, 0.f, 0.f};
#pragma unroll
        for (int rr = 0; rr < 4; rr++) {
            mn[rr] = fmaxf(mx[rr], t0[rr]);
            al[rr] = ex2((mx[rr] - mn[rr]) * SM_C);
            nmc[rr] = -mn[rr] * SM_C;
        }

#pragma unroll
        for (int im = 0; im < 2; im++)
#pragma unroll
            for (int tn = 0; tn < 8; tn++) {
                s[im][tn][0] = ex2(fmaf(s[im][tn][0], SM_C, nmc[im*2]));
                s[im][tn][1] = ex2(fmaf(s[im][tn][1], SM_C, nmc[im*2]));
                s[im][tn][2] = ex2(fmaf(s[im][tn][2], SM_C, nmc[im*2+1]));
                s[im][tn][3] = ex2(fmaf(s[im][tn][3], SM_C, nmc[im*2+1]));
                rs[im*2]   += s[im][tn][0] + s[im][tn][1];
                rs[im*2+1] += s[im][tn][2] + s[im][tn][3];
            }
#pragma unroll
        for (int rr = 0; rr < 4; rr++) {
            rs[rr] += __shfl_xor_sync(0xffffffffu, rs[rr], 1);
            rs[rr] += __shfl_xor_sync(0xffffffffu, rs[rr], 2);
            li[rr] = li[rr] * al[rr] + rs[rr];
            mx[rr] = mn[rr];
        }
#pragma unroll
        for (int im = 0; im < 2; im++)
#pragma unroll
            for (int tn = 0; tn < 8; tn++) {
                ao[im][tn][0] *= al[im*2];   ao[im][tn][1] *= al[im*2];
                ao[im][tn][2] *= al[im*2+1]; ao[im][tn][3] *= al[im*2+1];
            }

        // O += P @ V (C-frag -> fp16 A-frag natively)
#pragma unroll
        for (int kc = 0; kc < 4; kc++) {
            uint32_t pa0[4] = { packh2(s[0][2*kc][0],   s[0][2*kc][1]),
                                packh2(s[0][2*kc][2],   s[0][2*kc][3]),
                                packh2(s[0][2*kc+1][0], s[0][2*kc+1][1]),
                                packh2(s[0][2*kc+1][2], s[0][2*kc+1][3]) };
            uint32_t pa1[4] = { packh2(s[1][2*kc][0],   s[1][2*kc][1]),
                                packh2(s[1][2*kc][2],   s[1][2*kc][3]),
                                packh2(s[1][2*kc+1][0], s[1][2*kc+1][1]),
                                packh2(s[1][2*kc+1][2], s[1][2*kc+1][3]) };
            const int c0o = ckv[2 * kc];
            const int c1o = ckv[2 * kc + 1];
#pragma unroll
            for (int tn = 0; tn < 8; tn++) {
                uint32_t bb[2];
                bb[0] = *(const uint32_t*)(vs + tn * 1024 + rbase + c0o);
                bb[1] = *(const uint32_t*)(vs + tn * 1024 + rbase + c1o);
                mma16(ao[0][tn], pa0, bb);
                mma16(ao[1][tn], pa1, bb);
            }
        }

        cp_wait<0>();
        __syncthreads();
    }

    // normalize + fp16 store to g_AO [B,S,D]
    int b = bh >> 4, h = bh & 15;
#pragma unroll
    for (int im = 0; im < 2; im++) {
        float i0 = 1.f / li[im*2], i1 = 1.f / li[im*2+1];
        size_t srow = (size_t)qt * 128 + w * 32 + im * 16 + gid;
        __half* O0 = g_AO + ((size_t)b * SEQ + srow) * DM + h * HD + tg * 2;
        __half* O1 = O0 + (size_t)8 * DM;
#pragma unroll
        for (int tn = 0; tn < 8; tn++) {
            *reinterpret_cast<uint32_t*>(O0 + tn * 8) =
                packh2(ao[im][tn][0] * i0, ao[im][tn][1] * i0);
            *reinterpret_cast<uint32_t*>(O1 + tn * 8) =
                packh2(ao[im][tn][2] * i1, ao[im][tn][3] * i1);
        }
    }
}

// ---------------------------------------------------------------------------
extern "C" void kernel_launch(void* const* d_in, const int* in_sizes, int n_in,
                              void* d_out, int out_size) {
    const float* q  = (const float*)d_in[0];
    const float* k  = (const float*)d_in[1];
    const float* v  = (const float*)d_in[2];
    const float* Wq = (const float*)d_in[3];
    const float* bq = (const float*)d_in[4];
    const float* Wk = (const float*)d_in[5];
    const float* bk = (const float*)d_in[6];
    const float* Wv = (const float*)d_in[7];
    const float* bv = (const float*)d_in[8];
    const float* Wo = (const float*)d_in[9];
    const float* bo = (const float*)d_in[10];
    float* out = (float*)d_out;

    cudaFuncSetAttribute(qkv_kernel, cudaFuncAttributeMaxDynamicSharedMemorySize,
                         GEMM_SMEM_BYTES);
    cudaFuncSetAttribute(oproj_kernel, cudaFuncAttributeMaxDynamicSharedMemorySize,
                         GEMM_SMEM_BYTES);

    prep_kernel<<<dim3(4096, 8), 256>>>((const float4*)q, (const float4*)k,
                                        (const float4*)v, (const float4*)Wq,
                                        (const float4*)Wk, (const float4*)Wv,
                                        (const float4*)Wo);

    qkv_kernel<<<dim3(32, 8, 3), 256, GEMM_SMEM_BYTES>>>(bq, bk, bv);
    flash_kernel<<<dim3(8, 64), 128>>>();
    oproj_kernel<<<dim3(32, 8), 256, GEMM_SMEM_BYTES>>>(bo, out);
}